// round 1
// baseline (speedup 1.0000x reference)
#include <cuda_runtime.h>
#include <math.h>

// ---------------- problem constants ----------------
#define SEQ        2048
#define DIM        2048
#define DIM_INNER  4096
#define D_STATE    64
#define D_CONV     4
#define HEADDIM    128
#define NHEADS     32
#define CHUNK      256
#define NCHUNK     (SEQ / CHUNK)          // 8
#define CONV_DIM   (DIM_INNER + 2 * D_STATE)      // 4224
#define D_IN_PROJ  (2 * DIM_INNER + 2 * D_STATE + NHEADS)  // 8352

// ---------------- scratch (device globals; no allocation allowed) -------------
__device__ float g_zxbcdt[SEQ * D_IN_PROJ];          // 68.4 MB
__device__ float g_dt   [SEQ * NHEADS];
__device__ float g_dA   [SEQ * NHEADS];
__device__ float g_xs   [SEQ * DIM_INNER];
__device__ float g_xdt  [SEQ * DIM_INNER];
__device__ float g_B    [SEQ * D_STATE];
__device__ float g_C    [SEQ * D_STATE];
__device__ float g_Acs  [NCHUNK * NHEADS * CHUNK];
__device__ float g_Alast[NCHUNK * NHEADS];
__device__ float g_states[NCHUNK * NHEADS * HEADDIM * D_STATE];  // 8.4 MB
__device__ float g_sprev [NCHUNK * NHEADS * HEADDIM * D_STATE];
__device__ float g_y    [SEQ * DIM_INNER];           // y, then g (in place)

__device__ __forceinline__ float siluf(float v) {
    return v / (1.0f + expf(-v));
}
__device__ __forceinline__ float softplusf(float v) {
    return (v > 20.0f) ? v : log1pf(expf(v));
}

// ---------------- generic SGEMM: C[M,N] = A[M,K] * B[N,K]^T ----------------
// 128x128 block tile, BK=8, 256 threads, 8x8 per thread.
#define TBM 128
#define TBN 128
#define TBK 8

__global__ void __launch_bounds__(256, 2)
sgemm_nt(const float* __restrict__ A, const float* __restrict__ B,
         float* __restrict__ C, int M, int N, int K) {
    __shared__ float As[TBK][TBM];
    __shared__ float Bs[TBK][TBN];

    const int tid = threadIdx.x;
    const int m0 = blockIdx.y * TBM;
    const int n0 = blockIdx.x * TBN;
    const int tx = tid & 15;            // 0..15 -> n
    const int ty = tid >> 4;            // 0..15 -> m
    const int lrow = tid >> 1;          // 0..127
    const int lcol = (tid & 1) * 4;     // 0 or 4

    float acc[8][8];
#pragma unroll
    for (int i = 0; i < 8; i++)
#pragma unroll
        for (int j = 0; j < 8; j++) acc[i][j] = 0.0f;

    for (int k0 = 0; k0 < K; k0 += TBK) {
        float4 av = *(const float4*)&A[(m0 + lrow) * K + k0 + lcol];
        As[lcol + 0][lrow] = av.x;
        As[lcol + 1][lrow] = av.y;
        As[lcol + 2][lrow] = av.z;
        As[lcol + 3][lrow] = av.w;
        float4 bv = make_float4(0.f, 0.f, 0.f, 0.f);
        if (n0 + lrow < N)
            bv = *(const float4*)&B[(n0 + lrow) * K + k0 + lcol];
        Bs[lcol + 0][lrow] = bv.x;
        Bs[lcol + 1][lrow] = bv.y;
        Bs[lcol + 2][lrow] = bv.z;
        Bs[lcol + 3][lrow] = bv.w;
        __syncthreads();

#pragma unroll
        for (int kk = 0; kk < TBK; kk++) {
            float a[8], b[8];
            float4 a0 = *(const float4*)&As[kk][ty * 8];
            float4 a1 = *(const float4*)&As[kk][ty * 8 + 4];
            float4 b0 = *(const float4*)&Bs[kk][tx * 8];
            float4 b1 = *(const float4*)&Bs[kk][tx * 8 + 4];
            a[0]=a0.x; a[1]=a0.y; a[2]=a0.z; a[3]=a0.w;
            a[4]=a1.x; a[5]=a1.y; a[6]=a1.z; a[7]=a1.w;
            b[0]=b0.x; b[1]=b0.y; b[2]=b0.z; b[3]=b0.w;
            b[4]=b1.x; b[5]=b1.y; b[6]=b1.z; b[7]=b1.w;
#pragma unroll
            for (int i = 0; i < 8; i++)
#pragma unroll
                for (int j = 0; j < 8; j++)
                    acc[i][j] = fmaf(a[i], b[j], acc[i][j]);
        }
        __syncthreads();
    }

#pragma unroll
    for (int i = 0; i < 8; i++) {
        int m = m0 + ty * 8 + i;
#pragma unroll
        for (int j = 0; j < 8; j++) {
            int n = n0 + tx * 8 + j;
            if (n < N) C[(long)m * N + n] = acc[i][j];
        }
    }
}

// ---------------- dt / dA ----------------
__global__ void dt_kernel(const float* __restrict__ dt_bias,
                          const float* __restrict__ A_log) {
    int idx = blockIdx.x * blockDim.x + threadIdx.x;
    if (idx >= SEQ * NHEADS) return;
    int l = idx / NHEADS, h = idx % NHEADS;
    float v = g_zxbcdt[l * D_IN_PROJ + (D_IN_PROJ - NHEADS) + h] + dt_bias[h];
    float sp = softplusf(v);
    g_dt[idx] = sp;
    g_dA[idx] = -expf(A_log[h]) * sp;
}

// ---------------- causal depthwise conv + SiLU + split ----------------
__global__ void conv_kernel(const float* __restrict__ conv_w,
                            const float* __restrict__ conv_b) {
    int idx = blockIdx.x * blockDim.x + threadIdx.x;
    if (idx >= SEQ * CONV_DIM) return;
    int l = idx / CONV_DIM, ch = idx % CONV_DIM;
    float acc = conv_b[ch];
#pragma unroll
    for (int k = 0; k < D_CONV; k++) {
        int ls = l - (D_CONV - 1) + k;
        if (ls >= 0)
            acc += g_zxbcdt[ls * D_IN_PROJ + DIM_INNER + ch] * conv_w[ch * D_CONV + k];
    }
    float v = siluf(acc);
    if (ch < DIM_INNER) {
        int h = ch >> 7;
        g_xs [l * DIM_INNER + ch] = v;
        g_xdt[l * DIM_INNER + ch] = v * g_dt[l * NHEADS + h];
    } else if (ch < DIM_INNER + D_STATE) {
        g_B[l * D_STATE + (ch - DIM_INNER)] = v;
    } else {
        g_C[l * D_STATE + (ch - DIM_INNER - D_STATE)] = v;
    }
}

// ---------------- per-(chunk,head) inclusive cumsum of dA ----------------
__global__ void cumsum_kernel() {
    int ch = blockIdx.x;                 // c*NHEADS + h
    int c = ch / NHEADS, h = ch % NHEADS;
    int t = threadIdx.x;
    __shared__ float s[CHUNK];
    s[t] = g_dA[(c * CHUNK + t) * NHEADS + h];
    __syncthreads();
    for (int off = 1; off < CHUNK; off <<= 1) {
        float add = (t >= off) ? s[t - off] : 0.0f;
        __syncthreads();
        s[t] += add;
        __syncthreads();
    }
    g_Acs[ch * CHUNK + t] = s[t];
    if (t == CHUNK - 1) g_Alast[ch] = s[t];
}

// ---------------- chunk states: S[p,n] = sum_l decay(l)*xdt[l,p]*B[l,n] -----
__global__ void __launch_bounds__(256)
states_kernel() {
    int ch = blockIdx.x;                 // c*NHEADS + h
    int c = ch / NHEADS, h = ch % NHEADS;
    int t = threadIdx.x;
    int tp = t & 15;                     // p tile: tp*8..tp*8+7
    int tn = t >> 4;                     // n tile: tn*4..tn*4+3

    __shared__ float xw[32][HEADDIM];
    __shared__ float Bs[32][D_STATE];
    __shared__ float dec[32];

    float acc[8][4];
#pragma unroll
    for (int i = 0; i < 8; i++)
#pragma unroll
        for (int j = 0; j < 4; j++) acc[i][j] = 0.0f;

    float Al = g_Alast[ch];

    for (int lt = 0; lt < CHUNK; lt += 32) {
        if (t < 32) dec[t] = expf(Al - g_Acs[ch * CHUNK + lt + t]);
        __syncthreads();
#pragma unroll
        for (int r = 0; r < 16; r++) {
            int lin = t + r * 256;
            int l = lin >> 7, p = lin & 127;
            xw[l][p] = g_xdt[(c * CHUNK + lt + l) * DIM_INNER + h * HEADDIM + p] * dec[l];
        }
#pragma unroll
        for (int r = 0; r < 8; r++) {
            int lin = t + r * 256;
            int l = lin >> 6, n = lin & 63;
            Bs[l][n] = g_B[(c * CHUNK + lt + l) * D_STATE + n];
        }
        __syncthreads();
#pragma unroll 4
        for (int l = 0; l < 32; l++) {
            float a[8], b[4];
#pragma unroll
            for (int i = 0; i < 8; i++) a[i] = xw[l][tp * 8 + i];
#pragma unroll
            for (int j = 0; j < 4; j++) b[j] = Bs[l][tn * 4 + j];
#pragma unroll
            for (int i = 0; i < 8; i++)
#pragma unroll
                for (int j = 0; j < 4; j++)
                    acc[i][j] = fmaf(a[i], b[j], acc[i][j]);
        }
        __syncthreads();
    }
#pragma unroll
    for (int i = 0; i < 8; i++)
#pragma unroll
        for (int j = 0; j < 4; j++)
            g_states[ch * (HEADDIM * D_STATE) + (tp * 8 + i) * D_STATE + tn * 4 + j] = acc[i][j];
}

// ---------------- inter-chunk recurrence: S_in[c] ----------------
__global__ void sprev_kernel() {
    int idx = blockIdx.x * blockDim.x + threadIdx.x;
    if (idx >= NHEADS * HEADDIM * D_STATE) return;
    int h = idx / (HEADDIM * D_STATE);
    int r = idx % (HEADDIM * D_STATE);
    float S = 0.0f;
    for (int c = 0; c < NCHUNK; c++) {
        int ch = c * NHEADS + h;
        g_sprev[ch * (HEADDIM * D_STATE) + r] = S;
        S = expf(g_Alast[ch]) * S + g_states[ch * (HEADDIM * D_STATE) + r];
    }
}

// ---------------- Y kernel: Y_off + Y_diag + D*xs ----------------
// grid: (ltile 0..7, head, chunk); 256 threads; output tile 32 l x 128 p.
__global__ void __launch_bounds__(256)
y_kernel(const float* __restrict__ Dparam) {
    int lt = blockIdx.x, h = blockIdx.y, c = blockIdx.z;
    int ch = c * NHEADS + h;
    int l0 = lt * 32;
    int t = threadIdx.x;
    int pq = t & 31;                     // p = pq + 32*jj
    int lq = t >> 5;                     // l rows lq*4..lq*4+3

    __shared__ float Cs[32][65];
    __shared__ float Bs[32][65];
    __shared__ float xw[32][129];        // doubles as S^T[n][p]
    __shared__ float G [32][33];
    __shared__ float acsl[32], expAl[32], acss[32];

#pragma unroll
    for (int r = 0; r < 8; r++) {
        int lin = t + r * 256;
        int l = lin >> 6, n = lin & 63;
        Cs[l][n] = g_C[(c * CHUNK + l0 + l) * D_STATE + n];
    }
    if (t < 32) {
        float a = g_Acs[ch * CHUNK + l0 + t];
        acsl[t] = a;
        expAl[t] = expf(a);
    }
    __syncthreads();

    float acc[4][4];
#pragma unroll
    for (int i = 0; i < 4; i++)
#pragma unroll
        for (int j = 0; j < 4; j++) acc[i][j] = 0.0f;

    // ---- Stage A: Y_off = C @ S^T (depth 64, two 32-tiles) ----
    for (int nt = 0; nt < 2; nt++) {
#pragma unroll
        for (int r = 0; r < 16; r++) {
            int lin = t + r * 256;
            int p = lin >> 5, i = lin & 31;
            xw[i][p] = g_sprev[ch * (HEADDIM * D_STATE) + p * D_STATE + nt * 32 + i];
        }
        __syncthreads();
#pragma unroll 4
        for (int i = 0; i < 32; i++) {
            float cv[4], xv[4];
#pragma unroll
            for (int ii = 0; ii < 4; ii++) cv[ii] = Cs[lq * 4 + ii][nt * 32 + i];
#pragma unroll
            for (int jj = 0; jj < 4; jj++) xv[jj] = xw[i][pq + 32 * jj];
#pragma unroll
            for (int ii = 0; ii < 4; ii++)
#pragma unroll
                for (int jj = 0; jj < 4; jj++)
                    acc[ii][jj] = fmaf(cv[ii], xv[jj], acc[ii][jj]);
        }
        __syncthreads();
    }
    // scale by exp(A_cs[l])
#pragma unroll
    for (int ii = 0; ii < 4; ii++) {
        float e = expAl[lq * 4 + ii];
#pragma unroll
        for (int jj = 0; jj < 4; jj++) acc[ii][jj] *= e;
    }

    // ---- Stage B: Y_diag over s-tiles 0..lt ----
    for (int st = 0; st <= lt; st++) {
        int s0 = st * 32;
#pragma unroll
        for (int r = 0; r < 8; r++) {
            int lin = t + r * 256;
            int s = lin >> 6, n = lin & 63;
            Bs[s][n] = g_B[(c * CHUNK + s0 + s) * D_STATE + n];
        }
        if (t < 32) acss[t] = g_Acs[ch * CHUNK + s0 + t];
#pragma unroll
        for (int r = 0; r < 16; r++) {
            int lin = t + r * 256;
            int s = lin >> 7, p = lin & 127;
            xw[s][p] = g_xdt[(c * CHUNK + s0 + s) * DIM_INNER + h * HEADDIM + p];
        }
        __syncthreads();

        // compute G[l][s] = (C_l . B_s) * exp(Acs_l - Acs_s), masked
        {
            int l = t >> 3;
            int sb = (t & 7) * 4;
            float al = acsl[l];
#pragma unroll
            for (int e = 0; e < 4; e++) {
                int s = sb + e;
                float gv = 0.0f;
                if (st < lt || s <= l) {
                    float dotv = 0.0f;
#pragma unroll 8
                    for (int n = 0; n < D_STATE; n++)
                        dotv = fmaf(Cs[l][n], Bs[s][n], dotv);
                    gv = dotv * expf(al - acss[s]);
                }
                G[l][s] = gv;
            }
        }
        __syncthreads();

#pragma unroll 4
        for (int s = 0; s < 32; s++) {
            float gv[4], xv[4];
#pragma unroll
            for (int ii = 0; ii < 4; ii++) gv[ii] = G[lq * 4 + ii][s];
#pragma unroll
            for (int jj = 0; jj < 4; jj++) xv[jj] = xw[s][pq + 32 * jj];
#pragma unroll
            for (int ii = 0; ii < 4; ii++)
#pragma unroll
                for (int jj = 0; jj < 4; jj++)
                    acc[ii][jj] = fmaf(gv[ii], xv[jj], acc[ii][jj]);
        }
        __syncthreads();
    }

    // ---- Stage C: + D*xs, store y ----
    float Dh = Dparam[h];
#pragma unroll
    for (int ii = 0; ii < 4; ii++) {
        int lg = c * CHUNK + l0 + lq * 4 + ii;
#pragma unroll
        for (int jj = 0; jj < 4; jj++) {
            int p = pq + 32 * jj;
            int o = lg * DIM_INNER + h * HEADDIM + p;
            g_y[o] = acc[ii][jj] + g_xs[o] * Dh;
        }
    }
}

// ---------------- gated RMSNorm (in place on g_y) ----------------
__global__ void __launch_bounds__(256)
norm_kernel(const float* __restrict__ norm_w) {
    int l = blockIdx.x;
    int t = threadIdx.x;
    float vals[16];
    float ss = 0.0f;
#pragma unroll
    for (int r = 0; r < 16; r++) {
        int j = t + r * 256;
        float yv = g_y[l * DIM_INNER + j];
        float zv = g_zxbcdt[l * D_IN_PROJ + j];
        float gv = yv * siluf(zv);
        vals[r] = gv;
        ss += gv * gv;
    }
    // block reduce
    __shared__ float red[8];
#pragma unroll
    for (int off = 16; off > 0; off >>= 1)
        ss += __shfl_down_sync(0xffffffffu, ss, off);
    if ((t & 31) == 0) red[t >> 5] = ss;
    __syncthreads();
    float total;
    {
        float v = (t < 8) ? red[t] : 0.0f;
#pragma unroll
        for (int off = 4; off > 0; off >>= 1)
            v += __shfl_down_sync(0xffffffffu, v, off);
        if (t == 0) red[0] = v;
    }
    __syncthreads();
    total = red[0];
    float scale = rsqrtf(total / (float)DIM_INNER + 1e-5f);
#pragma unroll
    for (int r = 0; r < 16; r++) {
        int j = t + r * 256;
        g_y[l * DIM_INNER + j] = vals[r] * scale * norm_w[j];
    }
}

// ---------------- host launcher ----------------
extern "C" void kernel_launch(void* const* d_in, const int* in_sizes, int n_in,
                              void* d_out, int out_size) {
    const float* x        = (const float*)d_in[0];
    const float* in_w     = (const float*)d_in[1];
    const float* conv_w   = (const float*)d_in[2];
    const float* conv_b   = (const float*)d_in[3];
    const float* dt_bias  = (const float*)d_in[4];
    const float* A_log    = (const float*)d_in[5];
    const float* Dparam   = (const float*)d_in[6];
    const float* norm_w   = (const float*)d_in[7];
    const float* out_w    = (const float*)d_in[8];
    float* out            = (float*)d_out;

    float* zx;  cudaGetSymbolAddress((void**)&zx,  g_zxbcdt);
    float* gy;  cudaGetSymbolAddress((void**)&gy,  g_y);

    // 1. in_proj: zxbcdt[l, j] = sum_k x[l,k] * in_w[j,k]
    {
        dim3 grid((D_IN_PROJ + TBN - 1) / TBN, SEQ / TBM);
        sgemm_nt<<<grid, 256>>>(x, in_w, zx, SEQ, D_IN_PROJ, DIM);
    }
    // 2. dt / dA
    dt_kernel<<<(SEQ * NHEADS + 255) / 256, 256>>>(dt_bias, A_log);
    // 3. conv + silu + split
    conv_kernel<<<(SEQ * CONV_DIM + 255) / 256, 256>>>(conv_w, conv_b);
    // 4. cumsum per (chunk, head)
    cumsum_kernel<<<NCHUNK * NHEADS, CHUNK>>>();
    // 5. chunk states
    states_kernel<<<NCHUNK * NHEADS, 256>>>();
    // 6. inter-chunk recurrence
    sprev_kernel<<<(NHEADS * HEADDIM * D_STATE + 255) / 256, 256>>>();
    // 7. Y = Y_diag + Y_off + D*xs
    {
        dim3 grid(CHUNK / 32, NHEADS, NCHUNK);
        y_kernel<<<grid, 256>>>(Dparam);
    }
    // 8. gated RMSNorm (in place)
    norm_kernel<<<SEQ, 256>>>(norm_w);
    // 9. out_proj
    {
        dim3 grid(DIM / TBN, SEQ / TBM);
        sgemm_nt<<<grid, 256>>>(gy, out_w, out, SEQ, DIM, DIM_INNER);
    }
}

// round 3
// speedup vs baseline: 2.1517x; 2.1517x over previous
#include <cuda_runtime.h>
#include <math.h>
#include <stdint.h>

// ---------------- problem constants ----------------
#define SEQ        2048
#define DIM        2048
#define DIM_INNER  4096
#define D_STATE    64
#define D_CONV     4
#define HEADDIM    128
#define NHEADS     32
#define CHUNK      256
#define NCHUNK     (SEQ / CHUNK)          // 8
#define CONV_DIM   (DIM_INNER + 2 * D_STATE)      // 4224
#define D_IN_PROJ  (2 * DIM_INNER + 2 * D_STATE + NHEADS)  // 8352

// ---------------- scratch (device globals; no allocation allowed) -------------
__device__ __align__(128) float g_zxbcdt[SEQ * D_IN_PROJ];
__device__ float g_dt   [SEQ * NHEADS];
__device__ float g_dA   [SEQ * NHEADS];
__device__ float g_xs   [SEQ * DIM_INNER];
__device__ __align__(128) float g_xdt  [SEQ * DIM_INNER];
__device__ float g_B    [SEQ * D_STATE];
__device__ float g_C    [SEQ * D_STATE];
__device__ float g_Acs  [NCHUNK * NHEADS * CHUNK];
__device__ float g_Alast[NCHUNK * NHEADS];
__device__ float g_states[NCHUNK * NHEADS * HEADDIM * D_STATE];
__device__ float g_sprev [NCHUNK * NHEADS * HEADDIM * D_STATE];
__device__ __align__(128) float g_y    [SEQ * DIM_INNER];

__device__ __forceinline__ float siluf(float v) { return v / (1.0f + expf(-v)); }
__device__ __forceinline__ float softplusf(float v) { return (v > 20.0f) ? v : log1pf(expf(v)); }

__device__ __forceinline__ uint32_t f2tf32(float v) {
    uint32_t r;
    asm("cvt.rna.tf32.f32 %0, %1;" : "=r"(r) : "f"(v));
    return r;
}

// ============ tf32 mma.sync GEMM: C[M,N] = A[M,K] * B[N,K]^T ============
// 128x128 CTA tile, BK=16, 256 threads (8 warps, each 64x32), double buffered.
#define TBM 128
#define TBN 128
#define TBK 16
#define SPAD 4

__global__ void __launch_bounds__(256, 2)
tf32_gemm(const float* __restrict__ A, const float* __restrict__ B,
          float* __restrict__ C, int M, int N, int K) {
    __shared__ uint32_t As[2][TBK][TBM + SPAD];
    __shared__ uint32_t Bs[2][TBK][TBN + SPAD];

    const int tid  = threadIdx.x;
    const int lane = tid & 31;
    const int warp = tid >> 5;
    const int m0   = blockIdx.y * TBM;
    const int n0   = blockIdx.x * TBN;
    const int wm   = (warp >> 2) * 64;      // 0 or 64
    const int wn   = (warp & 3) * 32;       // 0,32,64,96
    const int ktiles = K / TBK;

    // loader mapping: each thread handles 2 float4 per operand tile
    const int lm0 = tid >> 2;               // rows 0..63
    const int lk  = (tid & 3) * 4;          // k offset 0,4,8,12

    float4 ra[2], rb[2];
    // prologue: load tile 0
    {
        const float* Ag = A + (long)(m0) * K;
        const float* Bg = B + (long)(n0) * K;
#pragma unroll
        for (int i = 0; i < 2; i++) {
            int m = lm0 + i * 64;
            ra[i] = *(const float4*)(Ag + (long)m * K + lk);
            int n = lm0 + i * 64;
            rb[i] = (n0 + n < N) ? *(const float4*)(Bg + (long)n * K + lk)
                                 : make_float4(0.f, 0.f, 0.f, 0.f);
        }
#pragma unroll
        for (int i = 0; i < 2; i++) {
            int m = lm0 + i * 64;
            As[0][lk + 0][m] = f2tf32(ra[i].x);
            As[0][lk + 1][m] = f2tf32(ra[i].y);
            As[0][lk + 2][m] = f2tf32(ra[i].z);
            As[0][lk + 3][m] = f2tf32(ra[i].w);
            Bs[0][lk + 0][m] = f2tf32(rb[i].x);
            Bs[0][lk + 1][m] = f2tf32(rb[i].y);
            Bs[0][lk + 2][m] = f2tf32(rb[i].z);
            Bs[0][lk + 3][m] = f2tf32(rb[i].w);
        }
    }
    __syncthreads();

    float acc[4][4][4];
#pragma unroll
    for (int i = 0; i < 4; i++)
#pragma unroll
        for (int j = 0; j < 4; j++)
#pragma unroll
            for (int r = 0; r < 4; r++) acc[i][j][r] = 0.0f;

    const int lr = lane >> 2;   // 0..7
    const int lc = lane & 3;    // 0..3

    for (int kt = 0; kt < ktiles; kt++) {
        int buf = kt & 1;
        // prefetch next tile (global)
        if (kt + 1 < ktiles) {
            int k0 = (kt + 1) * TBK;
            const float* Ag = A + (long)m0 * K + k0;
            const float* Bg = B + (long)n0 * K + k0;
#pragma unroll
            for (int i = 0; i < 2; i++) {
                int m = lm0 + i * 64;
                ra[i] = *(const float4*)(Ag + (long)m * K + lk);
                rb[i] = (n0 + m < N) ? *(const float4*)(Bg + (long)m * K + lk)
                                     : make_float4(0.f, 0.f, 0.f, 0.f);
            }
        }
        // compute from buf
#pragma unroll
        for (int kk = 0; kk < 2; kk++) {
            int kb = kk * 8;
            uint32_t afr[4][4], bfr[4][2];
#pragma unroll
            for (int mi = 0; mi < 4; mi++) {
                int mb = wm + mi * 16 + lr;
                afr[mi][0] = As[buf][kb + lc    ][mb];
                afr[mi][1] = As[buf][kb + lc    ][mb + 8];
                afr[mi][2] = As[buf][kb + lc + 4][mb];
                afr[mi][3] = As[buf][kb + lc + 4][mb + 8];
            }
#pragma unroll
            for (int ni = 0; ni < 4; ni++) {
                int nb = wn + ni * 8 + lr;
                bfr[ni][0] = Bs[buf][kb + lc    ][nb];
                bfr[ni][1] = Bs[buf][kb + lc + 4][nb];
            }
#pragma unroll
            for (int mi = 0; mi < 4; mi++)
#pragma unroll
                for (int ni = 0; ni < 4; ni++)
                    asm volatile(
                        "mma.sync.aligned.m16n8k8.row.col.f32.tf32.tf32.f32 "
                        "{%0,%1,%2,%3}, {%4,%5,%6,%7}, {%8,%9}, {%0,%1,%2,%3};"
                        : "+f"(acc[mi][ni][0]), "+f"(acc[mi][ni][1]),
                          "+f"(acc[mi][ni][2]), "+f"(acc[mi][ni][3])
                        : "r"(afr[mi][0]), "r"(afr[mi][1]),
                          "r"(afr[mi][2]), "r"(afr[mi][3]),
                          "r"(bfr[ni][0]), "r"(bfr[ni][1]));
        }
        // store next tile to other buffer
        if (kt + 1 < ktiles) {
            int nb = buf ^ 1;
            __syncthreads();
#pragma unroll
            for (int i = 0; i < 2; i++) {
                int m = lm0 + i * 64;
                As[nb][lk + 0][m] = f2tf32(ra[i].x);
                As[nb][lk + 1][m] = f2tf32(ra[i].y);
                As[nb][lk + 2][m] = f2tf32(ra[i].z);
                As[nb][lk + 3][m] = f2tf32(ra[i].w);
                Bs[nb][lk + 0][m] = f2tf32(rb[i].x);
                Bs[nb][lk + 1][m] = f2tf32(rb[i].y);
                Bs[nb][lk + 2][m] = f2tf32(rb[i].z);
                Bs[nb][lk + 3][m] = f2tf32(rb[i].w);
            }
            __syncthreads();
        }
    }

    // epilogue: C rows always in range (M multiple of 128); guard columns
#pragma unroll
    for (int mi = 0; mi < 4; mi++) {
        int r0 = m0 + wm + mi * 16 + lr;
#pragma unroll
        for (int ni = 0; ni < 4; ni++) {
            int ccol = n0 + wn + ni * 8 + lc * 2;
            if (ccol < N) {
                float* p0 = C + (long)r0 * N + ccol;
                float* p1 = C + (long)(r0 + 8) * N + ccol;
                p0[0] = acc[mi][ni][0];
                p0[1] = acc[mi][ni][1];
                p1[0] = acc[mi][ni][2];
                p1[1] = acc[mi][ni][3];
            }
        }
    }
}

// ---------------- dt / dA ----------------
__global__ void dt_kernel(const float* __restrict__ dt_bias,
                          const float* __restrict__ A_log) {
    int idx = blockIdx.x * blockDim.x + threadIdx.x;
    if (idx >= SEQ * NHEADS) return;
    int l = idx / NHEADS, h = idx % NHEADS;
    float v = g_zxbcdt[l * D_IN_PROJ + (D_IN_PROJ - NHEADS) + h] + dt_bias[h];
    float sp = softplusf(v);
    g_dt[idx] = sp;
    g_dA[idx] = -expf(A_log[h]) * sp;
}

// ---------------- causal depthwise conv + SiLU + split ----------------
__global__ void conv_kernel(const float* __restrict__ conv_w,
                            const float* __restrict__ conv_b) {
    int idx = blockIdx.x * blockDim.x + threadIdx.x;
    if (idx >= SEQ * CONV_DIM) return;
    int l = idx / CONV_DIM, ch = idx % CONV_DIM;
    float acc = conv_b[ch];
#pragma unroll
    for (int k = 0; k < D_CONV; k++) {
        int ls = l - (D_CONV - 1) + k;
        if (ls >= 0)
            acc += g_zxbcdt[ls * D_IN_PROJ + DIM_INNER + ch] * conv_w[ch * D_CONV + k];
    }
    float v = siluf(acc);
    if (ch < DIM_INNER) {
        int h = ch >> 7;
        g_xs [l * DIM_INNER + ch] = v;
        g_xdt[l * DIM_INNER + ch] = v * g_dt[l * NHEADS + h];
    } else if (ch < DIM_INNER + D_STATE) {
        g_B[l * D_STATE + (ch - DIM_INNER)] = v;
    } else {
        g_C[l * D_STATE + (ch - DIM_INNER - D_STATE)] = v;
    }
}

// ---------------- per-(chunk,head) inclusive cumsum of dA ----------------
__global__ void cumsum_kernel() {
    int ch = blockIdx.x;
    int c = ch / NHEADS, h = ch % NHEADS;
    int t = threadIdx.x;
    __shared__ float s[CHUNK];
    s[t] = g_dA[(c * CHUNK + t) * NHEADS + h];
    __syncthreads();
    for (int off = 1; off < CHUNK; off <<= 1) {
        float add = (t >= off) ? s[t - off] : 0.0f;
        __syncthreads();
        s[t] += add;
        __syncthreads();
    }
    g_Acs[ch * CHUNK + t] = s[t];
    if (t == CHUNK - 1) g_Alast[ch] = s[t];
}

// ---------------- chunk states ----------------
__global__ void __launch_bounds__(256)
states_kernel() {
    int ch = blockIdx.x;
    int c = ch / NHEADS, h = ch % NHEADS;
    int t = threadIdx.x;
    int tp = t & 15;
    int tn = t >> 4;

    __shared__ float xw[32][HEADDIM];
    __shared__ float Bs2[32][D_STATE];
    __shared__ float dec[32];

    float acc[8][4];
#pragma unroll
    for (int i = 0; i < 8; i++)
#pragma unroll
        for (int j = 0; j < 4; j++) acc[i][j] = 0.0f;

    float Al = g_Alast[ch];

    for (int lt = 0; lt < CHUNK; lt += 32) {
        if (t < 32) dec[t] = expf(Al - g_Acs[ch * CHUNK + lt + t]);
        __syncthreads();
#pragma unroll
        for (int r = 0; r < 16; r++) {
            int lin = t + r * 256;
            int l = lin >> 7, p = lin & 127;
            xw[l][p] = g_xdt[(c * CHUNK + lt + l) * DIM_INNER + h * HEADDIM + p] * dec[l];
        }
#pragma unroll
        for (int r = 0; r < 8; r++) {
            int lin = t + r * 256;
            int l = lin >> 6, n = lin & 63;
            Bs2[l][n] = g_B[(c * CHUNK + lt + l) * D_STATE + n];
        }
        __syncthreads();
#pragma unroll 4
        for (int l = 0; l < 32; l++) {
            float a[8], b[4];
#pragma unroll
            for (int i = 0; i < 8; i++) a[i] = xw[l][tp * 8 + i];
#pragma unroll
            for (int j = 0; j < 4; j++) b[j] = Bs2[l][tn * 4 + j];
#pragma unroll
            for (int i = 0; i < 8; i++)
#pragma unroll
                for (int j = 0; j < 4; j++)
                    acc[i][j] = fmaf(a[i], b[j], acc[i][j]);
        }
        __syncthreads();
    }
#pragma unroll
    for (int i = 0; i < 8; i++)
#pragma unroll
        for (int j = 0; j < 4; j++)
            g_states[ch * (HEADDIM * D_STATE) + (tp * 8 + i) * D_STATE + tn * 4 + j] = acc[i][j];
}

// ---------------- inter-chunk recurrence ----------------
__global__ void sprev_kernel() {
    int idx = blockIdx.x * blockDim.x + threadIdx.x;
    if (idx >= NHEADS * HEADDIM * D_STATE) return;
    int h = idx / (HEADDIM * D_STATE);
    int r = idx % (HEADDIM * D_STATE);
    float S = 0.0f;
    for (int c = 0; c < NCHUNK; c++) {
        int ch = c * NHEADS + h;
        g_sprev[ch * (HEADDIM * D_STATE) + r] = S;
        S = expf(g_Alast[ch]) * S + g_states[ch * (HEADDIM * D_STATE) + r];
    }
}

// ---------------- Y kernel ----------------
__global__ void __launch_bounds__(256)
y_kernel(const float* __restrict__ Dparam) {
    int lt = blockIdx.x, h = blockIdx.y, c = blockIdx.z;
    int ch = c * NHEADS + h;
    int l0 = lt * 32;
    int t = threadIdx.x;
    int pq = t & 31;
    int lq = t >> 5;

    __shared__ float Cs[32][65];
    __shared__ float Bs2[32][65];
    __shared__ float xw[32][129];
    __shared__ float G [32][33];
    __shared__ float acsl[32], expAl[32], acss[32];

#pragma unroll
    for (int r = 0; r < 8; r++) {
        int lin = t + r * 256;
        int l = lin >> 6, n = lin & 63;
        Cs[l][n] = g_C[(c * CHUNK + l0 + l) * D_STATE + n];
    }
    if (t < 32) {
        float a = g_Acs[ch * CHUNK + l0 + t];
        acsl[t] = a;
        expAl[t] = expf(a);
    }
    __syncthreads();

    float acc[4][4];
#pragma unroll
    for (int i = 0; i < 4; i++)
#pragma unroll
        for (int j = 0; j < 4; j++) acc[i][j] = 0.0f;

    for (int nt = 0; nt < 2; nt++) {
#pragma unroll
        for (int r = 0; r < 16; r++) {
            int lin = t + r * 256;
            int p = lin >> 5, i = lin & 31;
            xw[i][p] = g_sprev[ch * (HEADDIM * D_STATE) + p * D_STATE + nt * 32 + i];
        }
        __syncthreads();
#pragma unroll 4
        for (int i = 0; i < 32; i++) {
            float cv[4], xv[4];
#pragma unroll
            for (int ii = 0; ii < 4; ii++) cv[ii] = Cs[lq * 4 + ii][nt * 32 + i];
#pragma unroll
            for (int jj = 0; jj < 4; jj++) xv[jj] = xw[i][pq + 32 * jj];
#pragma unroll
            for (int ii = 0; ii < 4; ii++)
#pragma unroll
                for (int jj = 0; jj < 4; jj++)
                    acc[ii][jj] = fmaf(cv[ii], xv[jj], acc[ii][jj]);
        }
        __syncthreads();
    }
#pragma unroll
    for (int ii = 0; ii < 4; ii++) {
        float e = expAl[lq * 4 + ii];
#pragma unroll
        for (int jj = 0; jj < 4; jj++) acc[ii][jj] *= e;
    }

    for (int st = 0; st <= lt; st++) {
        int s0 = st * 32;
#pragma unroll
        for (int r = 0; r < 8; r++) {
            int lin = t + r * 256;
            int s = lin >> 6, n = lin & 63;
            Bs2[s][n] = g_B[(c * CHUNK + s0 + s) * D_STATE + n];
        }
        if (t < 32) acss[t] = g_Acs[ch * CHUNK + s0 + t];
#pragma unroll
        for (int r = 0; r < 16; r++) {
            int lin = t + r * 256;
            int s = lin >> 7, p = lin & 127;
            xw[s][p] = g_xdt[(c * CHUNK + s0 + s) * DIM_INNER + h * HEADDIM + p];
        }
        __syncthreads();

        {
            int l = t >> 3;
            int sb2 = (t & 7) * 4;
            float al = acsl[l];
#pragma unroll
            for (int e = 0; e < 4; e++) {
                int s = sb2 + e;
                float gv = 0.0f;
                if (st < lt || s <= l) {
                    float dotv = 0.0f;
#pragma unroll 8
                    for (int n = 0; n < D_STATE; n++)
                        dotv = fmaf(Cs[l][n], Bs2[s][n], dotv);
                    gv = dotv * expf(al - acss[s]);
                }
                G[l][s] = gv;
            }
        }
        __syncthreads();

#pragma unroll 4
        for (int s = 0; s < 32; s++) {
            float gv[4], xv[4];
#pragma unroll
            for (int ii = 0; ii < 4; ii++) gv[ii] = G[lq * 4 + ii][s];
#pragma unroll
            for (int jj = 0; jj < 4; jj++) xv[jj] = xw[s][pq + 32 * jj];
#pragma unroll
            for (int ii = 0; ii < 4; ii++)
#pragma unroll
                for (int jj = 0; jj < 4; jj++)
                    acc[ii][jj] = fmaf(gv[ii], xv[jj], acc[ii][jj]);
        }
        __syncthreads();
    }

    float Dh = Dparam[h];
#pragma unroll
    for (int ii = 0; ii < 4; ii++) {
        int lg = c * CHUNK + l0 + lq * 4 + ii;
#pragma unroll
        for (int jj = 0; jj < 4; jj++) {
            int p = pq + 32 * jj;
            int o = lg * DIM_INNER + h * HEADDIM + p;
            g_y[o] = acc[ii][jj] + g_xs[o] * Dh;
        }
    }
}

// ---------------- gated RMSNorm ----------------
__global__ void __launch_bounds__(256)
norm_kernel(const float* __restrict__ norm_w) {
    int l = blockIdx.x;
    int t = threadIdx.x;
    float vals[16];
    float ss = 0.0f;
#pragma unroll
    for (int r = 0; r < 16; r++) {
        int j = t + r * 256;
        float yv = g_y[l * DIM_INNER + j];
        float zv = g_zxbcdt[l * D_IN_PROJ + j];
        float gv = yv * siluf(zv);
        vals[r] = gv;
        ss += gv * gv;
    }
    __shared__ float red[8];
#pragma unroll
    for (int off = 16; off > 0; off >>= 1)
        ss += __shfl_down_sync(0xffffffffu, ss, off);
    if ((t & 31) == 0) red[t >> 5] = ss;
    __syncthreads();
    float total;
    {
        float v = (t < 8) ? red[t] : 0.0f;
#pragma unroll
        for (int off = 4; off > 0; off >>= 1)
            v += __shfl_down_sync(0xffffffffu, v, off);
        if (t == 0) red[0] = v;
    }
    __syncthreads();
    total = red[0];
    float scale = rsqrtf(total / (float)DIM_INNER + 1e-5f);
#pragma unroll
    for (int r = 0; r < 16; r++) {
        int j = t + r * 256;
        g_y[l * DIM_INNER + j] = vals[r] * scale * norm_w[j];
    }
}

// ---------------- host launcher ----------------
extern "C" void kernel_launch(void* const* d_in, const int* in_sizes, int n_in,
                              void* d_out, int out_size) {
    const float* x        = (const float*)d_in[0];
    const float* in_w     = (const float*)d_in[1];
    const float* conv_w   = (const float*)d_in[2];
    const float* conv_b   = (const float*)d_in[3];
    const float* dt_bias  = (const float*)d_in[4];
    const float* A_log    = (const float*)d_in[5];
    const float* Dparam   = (const float*)d_in[6];
    const float* norm_w   = (const float*)d_in[7];
    const float* out_w    = (const float*)d_in[8];
    float* out            = (float*)d_out;

    float* zx;  cudaGetSymbolAddress((void**)&zx,  g_zxbcdt);
    float* gy;  cudaGetSymbolAddress((void**)&gy,  g_y);

    // 1. in_proj: zxbcdt[l, j] = sum_k x[l,k] * in_w[j,k]   (tf32 mma.sync)
    {
        dim3 grid((D_IN_PROJ + TBN - 1) / TBN, SEQ / TBM);
        tf32_gemm<<<grid, 256>>>(x, in_w, zx, SEQ, D_IN_PROJ, DIM);
    }
    // 2. dt / dA
    dt_kernel<<<(SEQ * NHEADS + 255) / 256, 256>>>(dt_bias, A_log);
    // 3. conv + silu + split
    conv_kernel<<<(SEQ * CONV_DIM + 255) / 256, 256>>>(conv_w, conv_b);
    // 4. cumsum per (chunk, head)
    cumsum_kernel<<<NCHUNK * NHEADS, CHUNK>>>();
    // 5. chunk states
    states_kernel<<<NCHUNK * NHEADS, 256>>>();
    // 6. inter-chunk recurrence
    sprev_kernel<<<(NHEADS * HEADDIM * D_STATE + 255) / 256, 256>>>();
    // 7. Y = Y_diag + Y_off + D*xs
    {
        dim3 grid(CHUNK / 32, NHEADS, NCHUNK);
        y_kernel<<<grid, 256>>>(Dparam);
    }
    // 8. gated RMSNorm
    norm_kernel<<<SEQ, 256>>>(norm_w);
    // 9. out_proj (tf32 mma.sync)
    {
        dim3 grid(DIM / TBN, SEQ / TBM);
        tf32_gemm<<<grid, 256>>>(gy, out_w, out, SEQ, DIM, DIM_INNER);
    }
}

// round 4
// speedup vs baseline: 2.6647x; 1.2384x over previous
#include <cuda_runtime.h>
#include <math.h>
#include <stdint.h>

// ---------------- problem constants ----------------
#define SEQ        2048
#define DIM        2048
#define DIM_INNER  4096
#define D_STATE    64
#define D_CONV     4
#define HEADDIM    128
#define NHEADS     32
#define CHUNK      256
#define NCHUNK     (SEQ / CHUNK)          // 8
#define CONV_DIM   (DIM_INNER + 2 * D_STATE)      // 4224
#define D_IN_PROJ  (2 * DIM_INNER + 2 * D_STATE + NHEADS)  // 8352

// ---------------- scratch (device globals; no allocation allowed) -------------
__device__ __align__(128) float g_zxbcdt[SEQ * D_IN_PROJ];
__device__ float g_dt   [SEQ * NHEADS];
__device__ float g_dA   [SEQ * NHEADS];
__device__ float g_xs   [SEQ * DIM_INNER];
__device__ __align__(128) float g_xdt  [SEQ * DIM_INNER];
__device__ float g_B    [SEQ * D_STATE];
__device__ float g_C    [SEQ * D_STATE];
__device__ float g_Acs  [NCHUNK * NHEADS * CHUNK];
__device__ float g_Alast[NCHUNK * NHEADS];
__device__ float g_states[NCHUNK * NHEADS * HEADDIM * D_STATE];
__device__ float g_sprev [NCHUNK * NHEADS * HEADDIM * D_STATE];
__device__ __align__(128) float g_y    [SEQ * DIM_INNER];
// tf32-prerounded operands
__device__ __align__(128) float g_wA [D_IN_PROJ * DIM];     // in_proj weights
__device__ __align__(128) float g_wB [DIM * DIM_INNER];     // out_proj weights
__device__ __align__(128) float g_xr [SEQ * DIM];           // rounded x

__device__ __forceinline__ float siluf(float v) { return v / (1.0f + expf(-v)); }
__device__ __forceinline__ float softplusf(float v) { return (v > 20.0f) ? v : log1pf(expf(v)); }

__device__ __forceinline__ float tf32r(float v) {
    float r;
    asm("{ .reg .b32 t; cvt.rna.tf32.f32 t, %1; mov.b32 %0, t; }" : "=f"(r) : "f"(v));
    return r;
}

// ---------------- tf32 pre-rounding pass ----------------
__global__ void round_tf32_kernel(const float* __restrict__ in, float* __restrict__ out, int n) {
    int i = (blockIdx.x * blockDim.x + threadIdx.x) * 4;
    if (i >= n) return;
    float4 v = *(const float4*)(in + i);
    v.x = tf32r(v.x); v.y = tf32r(v.y); v.z = tf32r(v.z); v.w = tf32r(v.w);
    *(float4*)(out + i) = v;
}

// ============ tf32 mma.sync GEMM, cp.async 4-stage: C[M,N]=A[M,K]*B[N,K]^T ====
// Inputs MUST be pre-rounded to tf32 (rna); HW truncation is then exact.
#define TBM   128
#define TBN   128
#define TBK   16
#define NSTG  4
#define ROWP  20                        // row stride in floats (bank-conflict-free)
#define STGF  (TBM * ROWP)              // floats per operand per stage (2560)
#define GEMM_SMEM (2 * NSTG * STGF * 4) // 81920 bytes

__global__ void __launch_bounds__(256, 2)
tf32_gemm(const float* __restrict__ A, const float* __restrict__ B,
          float* __restrict__ C, int M, int N, int K) {
    extern __shared__ float sm[];
    float* Asm = sm;                    // [NSTG][TBM][ROWP]
    float* Bsm = sm + NSTG * STGF;

    const int tid  = threadIdx.x;
    const int lane = tid & 31;
    const int warp = tid >> 5;
    const int m0   = blockIdx.y * TBM;
    const int n0   = blockIdx.x * TBN;
    const int wm   = (warp >> 2) * 64;      // 0 or 64
    const int wn   = (warp & 3) * 32;       // 0,32,64,96
    const int lr   = lane >> 2;             // 0..7
    const int lc   = lane & 3;              // 0..3
    const int ktiles = K / TBK;

    const int lrow = tid >> 2;              // 0..63
    const int lck  = (tid & 3) * 4;         // k float offset 0,4,8,12

    uint32_t a_s0, b_s0;
    {
        uint32_t base;
        asm("{ .reg .u64 t; cvta.to.shared.u64 t, %1; cvt.u32.u64 %0, t; }"
            : "=r"(base) : "l"(sm));
        a_s0 = base;
        b_s0 = base + NSTG * STGF * 4;
    }

    // issue loads for k-tile kt into stage st
    auto issue = [&](int kt, int st) {
        const float* Ag = A + (long)m0 * K + kt * TBK;
        const float* Bg = B + (long)n0 * K + kt * TBK;
        uint32_t abase = a_s0 + st * STGF * 4;
        uint32_t bbase = b_s0 + st * STGF * 4;
#pragma unroll
        for (int i = 0; i < 2; i++) {
            int r = lrow + i * 64;
            uint32_t doff = r * ROWP * 4 + lck * 4;
            asm volatile("cp.async.cg.shared.global [%0], [%1], 16;"
                         :: "r"(abase + doff), "l"(Ag + (long)r * K + lck) : "memory");
            int sz = (n0 + r < N) ? 16 : 0;
            asm volatile("cp.async.cg.shared.global [%0], [%1], 16, %2;"
                         :: "r"(bbase + doff), "l"(Bg + (long)r * K + lck), "r"(sz) : "memory");
        }
        asm volatile("cp.async.commit_group;" ::: "memory");
    };

    // prologue: stages 0..NSTG-2
#pragma unroll
    for (int st = 0; st < NSTG - 1; st++) issue(st, st);

    float acc[4][4][4];
#pragma unroll
    for (int i = 0; i < 4; i++)
#pragma unroll
        for (int j = 0; j < 4; j++)
#pragma unroll
            for (int r = 0; r < 4; r++) acc[i][j][r] = 0.0f;

    for (int kt = 0; kt < ktiles; kt++) {
        int s = kt % NSTG;
        asm volatile("cp.async.wait_group %0;" :: "n"(NSTG - 2));
        __syncthreads();
        // issue next tile into the stage computed last iteration
        int nt = kt + NSTG - 1;
        if (nt < ktiles) issue(nt, nt % NSTG);
        else asm volatile("cp.async.commit_group;" ::: "memory");

        const float* As = Asm + s * STGF;
        const float* Bs = Bsm + s * STGF;
#pragma unroll
        for (int kk = 0; kk < 2; kk++) {
            int kb = kk * 8;
            uint32_t afr[4][4], bfr[4][2];
#pragma unroll
            for (int mi = 0; mi < 4; mi++) {
                int mb = wm + mi * 16 + lr;
                afr[mi][0] = __float_as_uint(As[(mb    ) * ROWP + kb + lc]);
                afr[mi][1] = __float_as_uint(As[(mb + 8) * ROWP + kb + lc]);
                afr[mi][2] = __float_as_uint(As[(mb    ) * ROWP + kb + lc + 4]);
                afr[mi][3] = __float_as_uint(As[(mb + 8) * ROWP + kb + lc + 4]);
            }
#pragma unroll
            for (int ni = 0; ni < 4; ni++) {
                int nb = wn + ni * 8 + lr;
                bfr[ni][0] = __float_as_uint(Bs[nb * ROWP + kb + lc]);
                bfr[ni][1] = __float_as_uint(Bs[nb * ROWP + kb + lc + 4]);
            }
#pragma unroll
            for (int mi = 0; mi < 4; mi++)
#pragma unroll
                for (int ni = 0; ni < 4; ni++)
                    asm volatile(
                        "mma.sync.aligned.m16n8k8.row.col.f32.tf32.tf32.f32 "
                        "{%0,%1,%2,%3}, {%4,%5,%6,%7}, {%8,%9}, {%0,%1,%2,%3};"
                        : "+f"(acc[mi][ni][0]), "+f"(acc[mi][ni][1]),
                          "+f"(acc[mi][ni][2]), "+f"(acc[mi][ni][3])
                        : "r"(afr[mi][0]), "r"(afr[mi][1]),
                          "r"(afr[mi][2]), "r"(afr[mi][3]),
                          "r"(bfr[ni][0]), "r"(bfr[ni][1]));
        }
    }

    // epilogue
#pragma unroll
    for (int mi = 0; mi < 4; mi++) {
        int r0 = m0 + wm + mi * 16 + lr;
#pragma unroll
        for (int ni = 0; ni < 4; ni++) {
            int ccol = n0 + wn + ni * 8 + lc * 2;
            if (ccol < N) {
                float* p0 = C + (long)r0 * N + ccol;
                float* p1 = C + (long)(r0 + 8) * N + ccol;
                p0[0] = acc[mi][ni][0];
                p0[1] = acc[mi][ni][1];
                p1[0] = acc[mi][ni][2];
                p1[1] = acc[mi][ni][3];
            }
        }
    }
}

// ---------------- dt / dA ----------------
__global__ void dt_kernel(const float* __restrict__ dt_bias,
                          const float* __restrict__ A_log) {
    int idx = blockIdx.x * blockDim.x + threadIdx.x;
    if (idx >= SEQ * NHEADS) return;
    int l = idx / NHEADS, h = idx % NHEADS;
    float v = g_zxbcdt[l * D_IN_PROJ + (D_IN_PROJ - NHEADS) + h] + dt_bias[h];
    float sp = softplusf(v);
    g_dt[idx] = sp;
    g_dA[idx] = -expf(A_log[h]) * sp;
}

// ---------------- causal depthwise conv + SiLU + split ----------------
__global__ void conv_kernel(const float* __restrict__ conv_w,
                            const float* __restrict__ conv_b) {
    int idx = blockIdx.x * blockDim.x + threadIdx.x;
    if (idx >= SEQ * CONV_DIM) return;
    int l = idx / CONV_DIM, ch = idx % CONV_DIM;
    float acc = conv_b[ch];
#pragma unroll
    for (int k = 0; k < D_CONV; k++) {
        int ls = l - (D_CONV - 1) + k;
        if (ls >= 0)
            acc += g_zxbcdt[ls * D_IN_PROJ + DIM_INNER + ch] * conv_w[ch * D_CONV + k];
    }
    float v = siluf(acc);
    if (ch < DIM_INNER) {
        int h = ch >> 7;
        g_xs [l * DIM_INNER + ch] = v;
        g_xdt[l * DIM_INNER + ch] = v * g_dt[l * NHEADS + h];
    } else if (ch < DIM_INNER + D_STATE) {
        g_B[l * D_STATE + (ch - DIM_INNER)] = v;
    } else {
        g_C[l * D_STATE + (ch - DIM_INNER - D_STATE)] = v;
    }
}

// ---------------- per-(chunk,head) inclusive cumsum of dA ----------------
__global__ void cumsum_kernel() {
    int ch = blockIdx.x;
    int c = ch / NHEADS, h = ch % NHEADS;
    int t = threadIdx.x;
    __shared__ float s[CHUNK];
    s[t] = g_dA[(c * CHUNK + t) * NHEADS + h];
    __syncthreads();
    for (int off = 1; off < CHUNK; off <<= 1) {
        float add = (t >= off) ? s[t - off] : 0.0f;
        __syncthreads();
        s[t] += add;
        __syncthreads();
    }
    g_Acs[ch * CHUNK + t] = s[t];
    if (t == CHUNK - 1) g_Alast[ch] = s[t];
}

// ---------------- chunk states ----------------
__global__ void __launch_bounds__(256)
states_kernel() {
    int ch = blockIdx.x;
    int c = ch / NHEADS, h = ch % NHEADS;
    int t = threadIdx.x;
    int tp = t & 15;
    int tn = t >> 4;

    __shared__ float xw[32][HEADDIM];
    __shared__ float Bs2[32][D_STATE];
    __shared__ float dec[32];

    float acc[8][4];
#pragma unroll
    for (int i = 0; i < 8; i++)
#pragma unroll
        for (int j = 0; j < 4; j++) acc[i][j] = 0.0f;

    float Al = g_Alast[ch];

    for (int lt = 0; lt < CHUNK; lt += 32) {
        if (t < 32) dec[t] = expf(Al - g_Acs[ch * CHUNK + lt + t]);
        __syncthreads();
#pragma unroll
        for (int r = 0; r < 16; r++) {
            int lin = t + r * 256;
            int l = lin >> 7, p = lin & 127;
            xw[l][p] = g_xdt[(c * CHUNK + lt + l) * DIM_INNER + h * HEADDIM + p] * dec[l];
        }
#pragma unroll
        for (int r = 0; r < 8; r++) {
            int lin = t + r * 256;
            int l = lin >> 6, n = lin & 63;
            Bs2[l][n] = g_B[(c * CHUNK + lt + l) * D_STATE + n];
        }
        __syncthreads();
#pragma unroll 4
        for (int l = 0; l < 32; l++) {
            float a[8], b[4];
#pragma unroll
            for (int i = 0; i < 8; i++) a[i] = xw[l][tp * 8 + i];
#pragma unroll
            for (int j = 0; j < 4; j++) b[j] = Bs2[l][tn * 4 + j];
#pragma unroll
            for (int i = 0; i < 8; i++)
#pragma unroll
                for (int j = 0; j < 4; j++)
                    acc[i][j] = fmaf(a[i], b[j], acc[i][j]);
        }
        __syncthreads();
    }
#pragma unroll
    for (int i = 0; i < 8; i++)
#pragma unroll
        for (int j = 0; j < 4; j++)
            g_states[ch * (HEADDIM * D_STATE) + (tp * 8 + i) * D_STATE + tn * 4 + j] = acc[i][j];
}

// ---------------- inter-chunk recurrence ----------------
__global__ void sprev_kernel() {
    int idx = blockIdx.x * blockDim.x + threadIdx.x;
    if (idx >= NHEADS * HEADDIM * D_STATE) return;
    int h = idx / (HEADDIM * D_STATE);
    int r = idx % (HEADDIM * D_STATE);
    float S = 0.0f;
    for (int c = 0; c < NCHUNK; c++) {
        int ch = c * NHEADS + h;
        g_sprev[ch * (HEADDIM * D_STATE) + r] = S;
        S = expf(g_Alast[ch]) * S + g_states[ch * (HEADDIM * D_STATE) + r];
    }
}

// ---------------- Y kernel ----------------
__global__ void __launch_bounds__(256)
y_kernel(const float* __restrict__ Dparam) {
    int lt = blockIdx.x, h = blockIdx.y, c = blockIdx.z;
    int ch = c * NHEADS + h;
    int l0 = lt * 32;
    int t = threadIdx.x;
    int pq = t & 31;
    int lq = t >> 5;

    __shared__ float Cs[32][65];
    __shared__ float Bs2[32][65];
    __shared__ float xw[32][129];
    __shared__ float G [32][33];
    __shared__ float acsl[32], expAl[32], acss[32];

#pragma unroll
    for (int r = 0; r < 8; r++) {
        int lin = t + r * 256;
        int l = lin >> 6, n = lin & 63;
        Cs[l][n] = g_C[(c * CHUNK + l0 + l) * D_STATE + n];
    }
    if (t < 32) {
        float a = g_Acs[ch * CHUNK + l0 + t];
        acsl[t] = a;
        expAl[t] = expf(a);
    }
    __syncthreads();

    float acc[4][4];
#pragma unroll
    for (int i = 0; i < 4; i++)
#pragma unroll
        for (int j = 0; j < 4; j++) acc[i][j] = 0.0f;

    for (int nt = 0; nt < 2; nt++) {
#pragma unroll
        for (int r = 0; r < 16; r++) {
            int lin = t + r * 256;
            int p = lin >> 5, i = lin & 31;
            xw[i][p] = g_sprev[ch * (HEADDIM * D_STATE) + p * D_STATE + nt * 32 + i];
        }
        __syncthreads();
#pragma unroll 4
        for (int i = 0; i < 32; i++) {
            float cv[4], xv[4];
#pragma unroll
            for (int ii = 0; ii < 4; ii++) cv[ii] = Cs[lq * 4 + ii][nt * 32 + i];
#pragma unroll
            for (int jj = 0; jj < 4; jj++) xv[jj] = xw[i][pq + 32 * jj];
#pragma unroll
            for (int ii = 0; ii < 4; ii++)
#pragma unroll
                for (int jj = 0; jj < 4; jj++)
                    acc[ii][jj] = fmaf(cv[ii], xv[jj], acc[ii][jj]);
        }
        __syncthreads();
    }
#pragma unroll
    for (int ii = 0; ii < 4; ii++) {
        float e = expAl[lq * 4 + ii];
#pragma unroll
        for (int jj = 0; jj < 4; jj++) acc[ii][jj] *= e;
    }

    for (int st = 0; st <= lt; st++) {
        int s0 = st * 32;
#pragma unroll
        for (int r = 0; r < 8; r++) {
            int lin = t + r * 256;
            int s = lin >> 6, n = lin & 63;
            Bs2[s][n] = g_B[(c * CHUNK + s0 + s) * D_STATE + n];
        }
        if (t < 32) acss[t] = g_Acs[ch * CHUNK + s0 + t];
#pragma unroll
        for (int r = 0; r < 16; r++) {
            int lin = t + r * 256;
            int s = lin >> 7, p = lin & 127;
            xw[s][p] = g_xdt[(c * CHUNK + s0 + s) * DIM_INNER + h * HEADDIM + p];
        }
        __syncthreads();

        {
            int l = t >> 3;
            int sb2 = (t & 7) * 4;
            float al = acsl[l];
#pragma unroll
            for (int e = 0; e < 4; e++) {
                int s = sb2 + e;
                float gv = 0.0f;
                if (st < lt || s <= l) {
                    float dotv = 0.0f;
#pragma unroll 8
                    for (int n = 0; n < D_STATE; n++)
                        dotv = fmaf(Cs[l][n], Bs2[s][n], dotv);
                    gv = dotv * expf(al - acss[s]);
                }
                G[l][s] = gv;
            }
        }
        __syncthreads();

#pragma unroll 4
        for (int s = 0; s < 32; s++) {
            float gv[4], xv[4];
#pragma unroll
            for (int ii = 0; ii < 4; ii++) gv[ii] = G[lq * 4 + ii][s];
#pragma unroll
            for (int jj = 0; jj < 4; jj++) xv[jj] = xw[s][pq + 32 * jj];
#pragma unroll
            for (int ii = 0; ii < 4; ii++)
#pragma unroll
                for (int jj = 0; jj < 4; jj++)
                    acc[ii][jj] = fmaf(gv[ii], xv[jj], acc[ii][jj]);
        }
        __syncthreads();
    }

    float Dh = Dparam[h];
#pragma unroll
    for (int ii = 0; ii < 4; ii++) {
        int lg = c * CHUNK + l0 + lq * 4 + ii;
#pragma unroll
        for (int jj = 0; jj < 4; jj++) {
            int p = pq + 32 * jj;
            int o = lg * DIM_INNER + h * HEADDIM + p;
            g_y[o] = acc[ii][jj] + g_xs[o] * Dh;
        }
    }
}

// ---------------- gated RMSNorm (stores tf32-rounded for GEMM2) ----------------
__global__ void __launch_bounds__(256)
norm_kernel(const float* __restrict__ norm_w) {
    int l = blockIdx.x;
    int t = threadIdx.x;
    float vals[16];
    float ss = 0.0f;
#pragma unroll
    for (int r = 0; r < 16; r++) {
        int j = t + r * 256;
        float yv = g_y[l * DIM_INNER + j];
        float zv = g_zxbcdt[l * D_IN_PROJ + j];
        float gv = yv * siluf(zv);
        vals[r] = gv;
        ss += gv * gv;
    }
    __shared__ float red[8];
#pragma unroll
    for (int off = 16; off > 0; off >>= 1)
        ss += __shfl_down_sync(0xffffffffu, ss, off);
    if ((t & 31) == 0) red[t >> 5] = ss;
    __syncthreads();
    float total;
    {
        float v = (t < 8) ? red[t] : 0.0f;
#pragma unroll
        for (int off = 4; off > 0; off >>= 1)
            v += __shfl_down_sync(0xffffffffu, v, off);
        if (t == 0) red[0] = v;
    }
    __syncthreads();
    total = red[0];
    float scale = rsqrtf(total / (float)DIM_INNER + 1e-5f);
#pragma unroll
    for (int r = 0; r < 16; r++) {
        int j = t + r * 256;
        g_y[l * DIM_INNER + j] = tf32r(vals[r] * scale * norm_w[j]);
    }
}

// ---------------- host launcher ----------------
extern "C" void kernel_launch(void* const* d_in, const int* in_sizes, int n_in,
                              void* d_out, int out_size) {
    const float* x        = (const float*)d_in[0];
    const float* in_w     = (const float*)d_in[1];
    const float* conv_w   = (const float*)d_in[2];
    const float* conv_b   = (const float*)d_in[3];
    const float* dt_bias  = (const float*)d_in[4];
    const float* A_log    = (const float*)d_in[5];
    const float* Dparam   = (const float*)d_in[6];
    const float* norm_w   = (const float*)d_in[7];
    const float* out_w    = (const float*)d_in[8];
    float* out            = (float*)d_out;

    float* zx;  cudaGetSymbolAddress((void**)&zx,  g_zxbcdt);
    float* gy;  cudaGetSymbolAddress((void**)&gy,  g_y);
    float* wA;  cudaGetSymbolAddress((void**)&wA,  g_wA);
    float* wB;  cudaGetSymbolAddress((void**)&wB,  g_wB);
    float* xr;  cudaGetSymbolAddress((void**)&xr,  g_xr);

    cudaFuncSetAttribute(tf32_gemm, cudaFuncAttributeMaxDynamicSharedMemorySize, GEMM_SMEM);

    // 0. pre-round GEMM operands to tf32 (rna)
    round_tf32_kernel<<<(D_IN_PROJ * DIM / 4 + 255) / 256, 256>>>(in_w, wA, D_IN_PROJ * DIM);
    round_tf32_kernel<<<(SEQ * DIM / 4 + 255) / 256, 256>>>(x, xr, SEQ * DIM);
    round_tf32_kernel<<<(DIM * DIM_INNER / 4 + 255) / 256, 256>>>(out_w, wB, DIM * DIM_INNER);

    // 1. in_proj (tf32 mma.sync, cp.async pipelined)
    {
        dim3 grid((D_IN_PROJ + TBN - 1) / TBN, SEQ / TBM);
        tf32_gemm<<<grid, 256, GEMM_SMEM>>>(xr, wA, zx, SEQ, D_IN_PROJ, DIM);
    }
    // 2. dt / dA
    dt_kernel<<<(SEQ * NHEADS + 255) / 256, 256>>>(dt_bias, A_log);
    // 3. conv + silu + split
    conv_kernel<<<(SEQ * CONV_DIM + 255) / 256, 256>>>(conv_w, conv_b);
    // 4. cumsum per (chunk, head)
    cumsum_kernel<<<NCHUNK * NHEADS, CHUNK>>>();
    // 5. chunk states
    states_kernel<<<NCHUNK * NHEADS, 256>>>();
    // 6. inter-chunk recurrence
    sprev_kernel<<<(NHEADS * HEADDIM * D_STATE + 255) / 256, 256>>>();
    // 7. Y = Y_diag + Y_off + D*xs
    {
        dim3 grid(CHUNK / 32, NHEADS, NCHUNK);
        y_kernel<<<grid, 256>>>(Dparam);
    }
    // 8. gated RMSNorm (rounds output to tf32 for GEMM2)
    norm_kernel<<<SEQ, 256>>>(norm_w);
    // 9. out_proj
    {
        dim3 grid(DIM / TBN, SEQ / TBM);
        tf32_gemm<<<grid, 256, GEMM_SMEM>>>(gy, wB, out, SEQ, DIM, DIM_INNER);
    }
}